// round 14
// baseline (speedup 1.0000x reference)
#include <cuda_runtime.h>
#include <float.h>

#define NPTS    8192
#define NB      4
#define NCHUNK  37                 // 4*4*37 = 592 = 148*4 blocks
#define NTILES  4
#define THREADS 256
#define IX      8                  // queries per thread; QTILE = 2048
#define GRID1   (NB * NTILES * NCHUNK)
#define NITEMS  (2 * NB * NPTS)    // 32768 row mins + 32768 col mins
#define RBLOCKS 32
#define PMAX    224                // fixed inner trip count (cnt <= 222, padded)

// Reversed-unsigned min scratch: armed state is 0 (static zero-init / re-zeroed
// by the reduce kernel each replay). atomicMax on key == float min.
__device__ unsigned g_min[NITEMS];

__device__ __forceinline__ unsigned encR(float f) {
    int b = __float_as_int(f);
    int e = (b >= 0) ? b : (b ^ 0x7fffffff);
    return 0x7fffffffu - (unsigned)e;
}
__device__ __forceinline__ float decR(unsigned r) {
    int e = (int)(0x7fffffffu - r);
    int b = (e >= 0) ? e : (e ^ 0x7fffffff);
    return __int_as_float(b);
}

__device__ __forceinline__ int redux_min_s32(int v) {
    int r;
    asm("redux.sync.min.s32 %0, %1, 0xffffffff;" : "=r"(r) : "r"(v));
    return r;
}

// Main pass. Block = (b, ntile, chunk). Stages <=222 y-points + sentinel pad.
// Per pair: u = ||y||^2 - 2 x.y (3 FFMA, row candidate; +wn folded in epilogue),
// d2 = u + wn (1 FADD, col candidate). Col warp-reduce = 1 redux.sync.min.s32
// on float bits (exact after the final clamp since d2 >= -eps).
// Warp w traverses points rotated by w*28 (mod 224): desynchronizes the 8
// warps' LDS/redux/STS bursts across the SMSP ports (min is order-invariant).
__global__ __launch_bounds__(THREADS, 4) void chamfer_main(
    const float* __restrict__ x, const float* __restrict__ y,
    float* __restrict__ out)
{
    __shared__ float4 sT[PMAX];
    __shared__ int    sCol[8][PMAX];

    const int bid   = blockIdx.x;
    const int chunk = bid % NCHUNK;
    const int ntile = (bid / NCHUNK) % NTILES;
    const int b     = bid / (NCHUNK * NTILES);

    if (bid == 0 && threadIdx.x == 0) *out = 0.0f;   // re-zero each replay

    const float* q = x + (size_t)b * NPTS * 3;
    const float* t = y + (size_t)b * NPTS * 3;

    const int j0  = (NPTS * chunk) / NCHUNK;
    const int j1  = (NPTS * (chunk + 1)) / NCHUNK;
    const int cnt = j1 - j0;                      // 221 or 222

    if (threadIdx.x < PMAX) {
        if (threadIdx.x < cnt) {
            const int j = j0 + threadIdx.x;
            const float tx = t[3 * j + 0];
            const float ty = t[3 * j + 1];
            const float tz = t[3 * j + 2];
            sT[threadIdx.x] = make_float4(tx, ty, tz,
                                          fmaf(tx, tx, fmaf(ty, ty, tz * tz)));
        } else {
            sT[threadIdx.x] = make_float4(0.f, 0.f, 0.f, 1e30f);  // sentinel
        }
    }
    __syncthreads();

    float ax[IX], ay[IX], az[IX], wn[IX], rm[IX];
    const int qbase = ntile * (THREADS * IX) + threadIdx.x;
#pragma unroll
    for (int i = 0; i < IX; ++i) {
        const int qi = qbase + i * THREADS;
        const float qx = q[3 * qi + 0];
        const float qy = q[3 * qi + 1];
        const float qz = q[3 * qi + 2];
        ax[i] = -2.0f * qx;
        ay[i] = -2.0f * qy;
        az[i] = -2.0f * qz;
        wn[i] = fmaf(qx, qx, fmaf(qy, qy, qz * qz));
        rm[i] = FLT_MAX;
    }

    const int wid  = threadIdx.x >> 5;
    const int lane = threadIdx.x & 31;
    const int off  = wid * 28;                    // per-warp rotation (mod PMAX)
    int* const colRow = sCol[wid];

#pragma unroll 2
    for (int pg = 0; pg < PMAX; pg += 4) {
        int m = pg + off;
        if (m >= PMAX) m -= PMAX;                 // wrap (2 alu ops / 4 points)
        int kb[4];
#pragma unroll
        for (int s = 0; s < 4; ++s) {
            const float4 T = sT[m + s];           // warp-broadcast LDS.128
            float tt[IX];
#pragma unroll
            for (int i = 0; i < IX; ++i) {
                const float u = fmaf(ax[i], T.x,
                                fmaf(ay[i], T.y,
                                fmaf(az[i], T.z, T.w)));
                rm[i] = fminf(rm[i], u);          // row candidate (wn added later)
                tt[i] = u + wn[i];                // full d2 (>= -eps): col candidate
            }
            float a0 = fminf(tt[0], tt[1]);
            float a1 = fminf(tt[2], tt[3]);
            float a2 = fminf(tt[4], tt[5]);
            float a3 = fminf(tt[6], tt[7]);
            const float tmin = fminf(fminf(a0, a1), fminf(a2, a3));
            kb[s] = redux_min_s32(__float_as_int(tmin));
        }
        if (lane == 0)
            *(int4*)&colRow[m] = make_int4(kb[0], kb[1], kb[2], kb[3]);
    }
    __syncthreads();

    // Row epilogue: fold +wn; scratch holds final row d2 mins.
    const int gq = b * NPTS + qbase;
#pragma unroll
    for (int i = 0; i < IX; ++i)
        atomicMax(&g_min[gq + i * THREADS], encR(rm[i] + wn[i]));

    // Col epilogue: combine 8 warps in int domain (same ordering argument).
    if (threadIdx.x < cnt) {
        int m = sCol[0][threadIdx.x];
#pragma unroll
        for (int w = 1; w < 8; ++w)
            m = min(m, sCol[w][threadIdx.x]);
        atomicMax(&g_min[NB * NPTS + b * NPTS + j0 + threadIdx.x],
                  encR(__int_as_float(m)));
    }
}

// Reduce 65536 L2-hot keys: decode, clamp, sum; re-zero scratch; one atomicAdd
// per block into out (zeroed by chamfer_main block 0).
__global__ __launch_bounds__(256) void chamfer_reduce(float* __restrict__ out)
{
    uint4* gm4 = (uint4*)g_min;
    float v = 0.0f;
#pragma unroll
    for (int r = 0; r < 2; ++r) {
        const int base = (blockIdx.x * 2 + r) * 256 + threadIdx.x;
        const uint4 k = gm4[base];
        gm4[base] = make_uint4(0u, 0u, 0u, 0u);        // re-arm for next replay
        v += fmaxf(decR(k.x), 0.0f) + fmaxf(decR(k.y), 0.0f)
           + fmaxf(decR(k.z), 0.0f) + fmaxf(decR(k.w), 0.0f);
    }

#pragma unroll
    for (int o = 16; o > 0; o >>= 1)
        v += __shfl_xor_sync(0xffffffffu, v, o);

    __shared__ float red[8];
    if ((threadIdx.x & 31) == 0) red[threadIdx.x >> 5] = v;
    __syncthreads();

    if (threadIdx.x == 0) {
        float s = red[0];
#pragma unroll
        for (int w = 1; w < 8; ++w) s += red[w];
        atomicAdd(out, s * (1.0f / ((float)NPTS * (float)NB)));
    }
}

extern "C" void kernel_launch(void* const* d_in, const int* in_sizes, int n_in,
                              void* d_out, int out_size)
{
    (void)in_sizes; (void)n_in; (void)out_size;
    const float* x = (const float*)d_in[0];
    const float* y = (const float*)d_in[1];
    float* out = (float*)d_out;

    chamfer_main<<<GRID1, THREADS>>>(x, y, out);
    chamfer_reduce<<<RBLOCKS, 256>>>(out);
}

// round 15
// speedup vs baseline: 1.1254x; 1.1254x over previous
#include <cuda_runtime.h>
#include <float.h>

#define NPTS    8192
#define NB      4
#define NCHUNK  37                 // 4*4*37 = 592 = 148*4 blocks
#define NTILES  4
#define THREADS 256
#define IX      8                  // queries per thread; QTILE = 2048
#define GRID1   (NB * NTILES * NCHUNK)
#define NITEMS  (2 * NB * NPTS)    // 32768 row mins + 32768 col mins
#define RBLOCKS 16
#define PMAX    224                // fixed inner trip count (cnt <= 222, padded)

// Reversed-unsigned min scratch: armed state is 0 (static zero-init / re-zeroed
// by the reduce kernel each replay). atomicMax on key == float min.
__device__ unsigned g_min[NITEMS];

__device__ __forceinline__ unsigned encR(float f) {
    int b = __float_as_int(f);
    int e = (b >= 0) ? b : (b ^ 0x7fffffff);
    return 0x7fffffffu - (unsigned)e;
}
__device__ __forceinline__ float decR(unsigned r) {
    int e = (int)(0x7fffffffu - r);
    int b = (e >= 0) ? e : (e ^ 0x7fffffff);
    return __int_as_float(b);
}

__device__ __forceinline__ int redux_min_s32(int v) {
    int r;
    asm("redux.sync.min.s32 %0, %1, 0xffffffff;" : "=r"(r) : "r"(v));
    return r;
}

// Main pass (converged: measured at 100% of the fma-pipe rt=2 ceiling).
// Block = (b, ntile, chunk). Stages <=222 y-points + sentinel pad.
// Per pair: u = ||y||^2 - 2 x.y (3 FFMA, row candidate; +wn folded in epilogue),
// d2 = u + wn (1 FADD, col candidate). Col warp-reduce = 1 redux.sync.min.s32
// on float bits (exact after the final clamp since d2 >= -eps).
// Loop body = 4 points (one STS.128 of 4 redux results), unrolled x2.
__global__ __launch_bounds__(THREADS, 4) void chamfer_main(
    const float* __restrict__ x, const float* __restrict__ y,
    float* __restrict__ out)
{
    __shared__ float4 sT[PMAX];
    __shared__ int    sCol[8][PMAX];

    const int bid   = blockIdx.x;
    const int chunk = bid % NCHUNK;
    const int ntile = (bid / NCHUNK) % NTILES;
    const int b     = bid / (NCHUNK * NTILES);

    if (bid == 0 && threadIdx.x == 0) *out = 0.0f;   // re-zero each replay

    const float* q = x + (size_t)b * NPTS * 3;
    const float* t = y + (size_t)b * NPTS * 3;

    const int j0  = (NPTS * chunk) / NCHUNK;
    const int j1  = (NPTS * (chunk + 1)) / NCHUNK;
    const int cnt = j1 - j0;                      // 221 or 222

    if (threadIdx.x < PMAX) {
        if (threadIdx.x < cnt) {
            const int j = j0 + threadIdx.x;
            const float tx = t[3 * j + 0];
            const float ty = t[3 * j + 1];
            const float tz = t[3 * j + 2];
            sT[threadIdx.x] = make_float4(tx, ty, tz,
                                          fmaf(tx, tx, fmaf(ty, ty, tz * tz)));
        } else {
            sT[threadIdx.x] = make_float4(0.f, 0.f, 0.f, 1e30f);  // sentinel
        }
    }
    __syncthreads();

    float ax[IX], ay[IX], az[IX], wn[IX], rm[IX];
    const int qbase = ntile * (THREADS * IX) + threadIdx.x;
#pragma unroll
    for (int i = 0; i < IX; ++i) {
        const int qi = qbase + i * THREADS;
        const float qx = q[3 * qi + 0];
        const float qy = q[3 * qi + 1];
        const float qz = q[3 * qi + 2];
        ax[i] = -2.0f * qx;
        ay[i] = -2.0f * qy;
        az[i] = -2.0f * qz;
        wn[i] = fmaf(qx, qx, fmaf(qy, qy, qz * qz));
        rm[i] = FLT_MAX;
    }

    const int wid  = threadIdx.x >> 5;
    const int lane = threadIdx.x & 31;
    int* const colRow = sCol[wid];

#pragma unroll 2
    for (int pg = 0; pg < PMAX; pg += 4) {
        int kb[4];
#pragma unroll
        for (int s = 0; s < 4; ++s) {
            const float4 T = sT[pg + s];        // warp-broadcast LDS.128
            float tt[IX];
#pragma unroll
            for (int i = 0; i < IX; ++i) {
                const float u = fmaf(ax[i], T.x,
                                fmaf(ay[i], T.y,
                                fmaf(az[i], T.z, T.w)));
                rm[i] = fminf(rm[i], u);        // row candidate (wn added later)
                tt[i] = u + wn[i];              // full d2 (>= -eps): col candidate
            }
            float a0 = fminf(tt[0], tt[1]);
            float a1 = fminf(tt[2], tt[3]);
            float a2 = fminf(tt[4], tt[5]);
            float a3 = fminf(tt[6], tt[7]);
            const float tmin = fminf(fminf(a0, a1), fminf(a2, a3));
            kb[s] = redux_min_s32(__float_as_int(tmin));
        }
        if (lane == 0)
            *(int4*)&colRow[pg] = make_int4(kb[0], kb[1], kb[2], kb[3]);
    }
    __syncthreads();

    // Row epilogue: fold +wn; scratch holds final row d2 mins.
    const int gq = b * NPTS + qbase;
#pragma unroll
    for (int i = 0; i < IX; ++i)
        atomicMax(&g_min[gq + i * THREADS], encR(rm[i] + wn[i]));

    // Col epilogue: combine 8 warps in int domain (same ordering argument).
    if (threadIdx.x < cnt) {
        int m = sCol[0][threadIdx.x];
#pragma unroll
        for (int w = 1; w < 8; ++w)
            m = min(m, sCol[w][threadIdx.x]);
        atomicMax(&g_min[NB * NPTS + b * NPTS + j0 + threadIdx.x],
                  encR(__int_as_float(m)));
    }
}

// Reduce 65536 L2-hot keys: decode, clamp, sum; re-zero scratch; one atomicAdd
// per block into out (zeroed by chamfer_main block 0).
__global__ __launch_bounds__(256) void chamfer_reduce(float* __restrict__ out)
{
    uint4* gm4 = (uint4*)g_min;
    float v = 0.0f;
#pragma unroll
    for (int r = 0; r < 4; ++r) {
        const int base = (blockIdx.x * 4 + r) * 256 + threadIdx.x;
        const uint4 k = gm4[base];
        gm4[base] = make_uint4(0u, 0u, 0u, 0u);        // re-arm for next replay
        v += fmaxf(decR(k.x), 0.0f) + fmaxf(decR(k.y), 0.0f)
           + fmaxf(decR(k.z), 0.0f) + fmaxf(decR(k.w), 0.0f);
    }

#pragma unroll
    for (int o = 16; o > 0; o >>= 1)
        v += __shfl_xor_sync(0xffffffffu, v, o);

    __shared__ float red[8];
    if ((threadIdx.x & 31) == 0) red[threadIdx.x >> 5] = v;
    __syncthreads();

    if (threadIdx.x == 0) {
        float s = red[0];
#pragma unroll
        for (int w = 1; w < 8; ++w) s += red[w];
        atomicAdd(out, s * (1.0f / ((float)NPTS * (float)NB)));
    }
}

extern "C" void kernel_launch(void* const* d_in, const int* in_sizes, int n_in,
                              void* d_out, int out_size)
{
    (void)in_sizes; (void)n_in; (void)out_size;
    const float* x = (const float*)d_in[0];
    const float* y = (const float*)d_in[1];
    float* out = (float*)d_out;

    chamfer_main<<<GRID1, THREADS>>>(x, y, out);
    chamfer_reduce<<<RBLOCKS, 256>>>(out);
}